// round 4
// baseline (speedup 1.0000x reference)
#include <cuda_runtime.h>
#include <cstdint>

// ---------------- problem constants ----------------
#define NATOMS   50000
#define S        7
#define NRBF     16
#define NPAIRS   28        // S*(S+1)/2
#define SUB      32        // NA*NZ
#define COLS     1008      // S*NRBF + NPAIRS*SUB
#define ANG_OFF  112       // S*NRBF
#define RC       0.51f
#define RMIN     0.08f
#define RCA      0.35f
#define RAMIN    0.08f
#define NA       8
#define NZ       4
#define ETA_R    1970.0f
#define ZETA     14.1f
#define PI_F     3.14159265358979323846f
#define PI_OVER_RC   (PI_F / RC)
#define PI_OVER_RCA  (PI_F / RCA)
#define DSTEP_R  0.026875f       // (RC-RMIN)/NRBF
#define DSTEP_A  0.03375f        // (RCA-RAMIN)/NA
#define ETA_A_LOG2E 1803.3688011112043f  // ETA_A * log2(e)

#define MAXP     1000000
#define PA_CONST 200000

// scratch (static device globals: allocation-free per harness rules)
__device__ float4         g_geo[PA_CONST];   // r_ij.xyz, d   (angular pairs only)
__device__ float2         g_aux[PA_CONST];   // fc_angular, 1/d
__device__ unsigned short g_spec[PA_CONST];  // (si<<3) | sj
__device__ uint2          g_base[MAXP];      // radial scatter bases (floats)

// ================= kernel A: zero-fill || per-pair precompute =================
__global__ __launch_bounds__(256)
void fusedA_kernel(const int* __restrict__ atom_index,
                   const int* __restrict__ pairs,   // [2, P]
                   const float* __restrict__ d_ij,  // [P]
                   const float* __restrict__ r_ij,  // [P,3]
                   float4* __restrict__ out4,
                   int P, int zblocks, int n4)
{
    if ((int)blockIdx.x < zblocks) {
        // zero-fill partition: grid-stride float4 stores
        int stride = zblocks * 256;
        for (int i = blockIdx.x * 256 + threadIdx.x; i < n4; i += stride)
            out4[i] = make_float4(0.f, 0.f, 0.f, 0.f);
        return;
    }
    int p = (blockIdx.x - zblocks) * 256 + threadIdx.x;
    if (p >= P) return;

    int i  = pairs[p];
    int j  = pairs[P + p];
    int si = atom_index[i];
    int sj = atom_index[j];
    float d = d_ij[p];

    g_base[p] = make_uint2((unsigned)(i * COLS + sj * NRBF),
                           (unsigned)(j * COLS + si * NRBF));

    if (p < PA_CONST) {
        float4 g;
        g.x = r_ij[3 * p + 0];
        g.y = r_ij[3 * p + 1];
        g.z = r_ij[3 * p + 2];
        g.w = d;
        g_geo[p]  = g;
        float fc = (d < RCA) ? (0.5f * __cosf(PI_OVER_RCA * d) + 0.5f) : 0.0f;
        g_aux[p]  = make_float2(fc, __fdividef(1.0f, d));
        g_spec[p] = (unsigned short)((si << 3) | sj);
    }
}

// ================= kernel B: angular || radial =================
__global__ __launch_bounds__(128)
void fusedB_kernel(const int* __restrict__ central,
                   const int* __restrict__ pidx,    // [2, T]
                   const int* __restrict__ sign12,  // [2, T]
                   const float* __restrict__ d_ij,
                   float* __restrict__ out,
                   int P, int T, int ablocks)
{
    if ((int)blockIdx.x < ablocks) {
        // ---------------- angular partition ----------------
        __shared__ float s_f1[128 * 4];   // pref * f1[zz]
        __shared__ float s_f2[128 * 8];   // f2[az]
        __shared__ int   s_base[128];

        int tid = threadIdx.x;
        int t   = blockIdx.x * 128 + tid;

        if (t < T) {
            int p0  = pidx[t];
            int p1  = pidx[T + t];
            int sg0 = sign12[t];
            int sg1 = sign12[T + t];
            int c   = central[t];

            float4 g0 = g_geo[p0];
            float4 g1 = g_geo[p1];
            float2 a0 = g_aux[p0];
            float2 a1 = g_aux[p1];

            float dot  = g0.x * g1.x + g0.y * g1.y + g0.z * g1.z;
            float ss   = (sg0 == sg1) ? 0.95f : -0.95f;
            float cosa = ss * dot * a0.y * a1.y;
            float sina = sqrtf(fmaxf(0.0f, 1.0f - cosa * cosa));
            float sd   = 0.5f * (g0.w + g1.w);
            float pref = 2.0f * a0.x * a1.x;

            // f1[zz] = ((1 + cos(angle - shfz))/2)^ZETA via angle-addition
            // cos/sin of (zz+0.5)*pi/4, folded as compile-time constants
            {
                const float CZ[4] = { 0.92387953251f,  0.38268343236f,
                                     -0.38268343236f, -0.92387953251f };
                const float SZ[4] = { 0.38268343236f,  0.92387953251f,
                                      0.92387953251f,  0.38268343236f };
                #pragma unroll
                for (int zz = 0; zz < NZ; zz++) {
                    float u = fmaxf(0.0f, fmaf(0.5f * CZ[zz], cosa,
                                          fmaf(0.5f * SZ[zz], sina, 0.5f)));
                    s_f1[tid * 4 + zz] = pref * exp2f(ZETA * __log2f(u));
                }
            }
            // f2[az] = exp(-ETA_A * (sd - shfa)^2)
            #pragma unroll
            for (int az = 0; az < NA; az++) {
                float dx = sd - (RAMIN + (float)az * DSTEP_A);
                s_f2[tid * 8 + az] = exp2f(-ETA_A_LOG2E * dx * dx);
            }

            int sp0 = g_spec[p0];
            int sp1 = g_spec[p1];
            int s0 = (sg0 > 0) ? (sp0 & 7) : (sp0 >> 3);
            int s1 = (sg1 > 0) ? (sp1 & 7) : (sp1 >> 3);
            int a  = min(s0, s1);
            int b  = max(s0, s1);
            int tri = a * S - ((a * (a - 1)) >> 1) + (b - a);
            s_base[tid] = c * COLS + ANG_OFF + tri * SUB;
        }
        __syncthreads();

        int warp = tid >> 5;
        int lane = tid & 31;
        int az = lane >> 2;   // 0..7
        int zz = lane & 3;    // 0..3

        int begin = warp * 32;
        int nv = T - (blockIdx.x * 128 + begin);
        if (nv > 32) nv = 32;

        for (int jj = 0; jj < nv; jj++) {
            int idx = begin + jj;
            float v = s_f1[idx * 4 + zz] * s_f2[idx * 8 + az];
            atomicAdd(out + s_base[idx] + lane, v);   // 128B coalesced RED
        }
    } else {
        // ---------------- radial partition: 16 lanes per pair ----------------
        int rtid = (blockIdx.x - ablocks) * 128 + threadIdx.x;
        int p = rtid >> 4;
        if (p >= P) return;
        int k = rtid & 15;

        float d = __ldg(d_ij + p);
        uint2 b = g_base[p];

        float fc = (d < RC) ? (0.5f * __cosf(PI_OVER_RC * d) + 0.5f) : 0.0f;
        float dx = d - (RMIN + (float)k * DSTEP_R);
        float term = 0.25f * fc * __expf(-ETA_R * dx * dx);

        atomicAdd(out + b.x + k, term);   // 64B coalesced RED
        atomicAdd(out + b.y + k, term);
    }
}

// ---------------- launch ----------------
extern "C" void kernel_launch(void* const* d_in, const int* in_sizes, int n_in,
                              void* d_out, int out_size)
{
    const int*   atom_index = (const int*)  d_in[0];
    const int*   pairs      = (const int*)  d_in[1];
    const float* d_ij       = (const float*)d_in[2];
    const float* r_ij       = (const float*)d_in[3];
    const int*   central    = (const int*)  d_in[4];
    const int*   pidx12     = (const int*)  d_in[5];
    const int*   sign12     = (const int*)  d_in[6];
    float* out = (float*)d_out;

    int P = in_sizes[2];      // pair count
    int T = in_sizes[4];      // triple count

    // kernel A: zero-fill || prep
    int n4 = out_size / 4;                      // out_size divisible by 4
    int zblocks = 2368;                         // 16 blocks/SM worth of zero work
    int pblocks = (P + 255) / 256;
    fusedA_kernel<<<zblocks + pblocks, 256>>>(atom_index, pairs, d_ij, r_ij,
                                              (float4*)d_out, P, zblocks, n4);

    // kernel B: angular || radial
    int ablocks = (T + 127) / 128;
    long long rthreads = (long long)P * 16;
    int rblocks = (int)((rthreads + 127) / 128);
    fusedB_kernel<<<ablocks + rblocks, 128>>>(central, pidx12, sign12, d_ij,
                                              out, P, T, ablocks);
}

// round 6
// speedup vs baseline: 1.1597x; 1.1597x over previous
#include <cuda_runtime.h>
#include <cstdint>

// ---------------- problem constants ----------------
#define NATOMS   50000
#define S        7
#define NRBF     16
#define NPAIRS   28        // S*(S+1)/2
#define SUB      32        // NA*NZ
#define COLS     1008      // S*NRBF + NPAIRS*SUB
#define ANG_OFF  112       // S*NRBF
#define RC       0.51f
#define RMIN     0.08f
#define RCA      0.35f
#define RAMIN    0.08f
#define NA       8
#define NZ       4
#define ETA_R    1970.0f
#define ZETA     14.1f
#define PI_F     3.14159265358979323846f
#define PI_OVER_RC   (PI_F / RC)
#define PI_OVER_RCA  (PI_F / RCA)
#define DSTEP_R  0.026875f       // (RC-RMIN)/NRBF
#define DSTEP_A  0.03375f        // (RCA-RAMIN)/NA
#define ETA_A_LOG2E 1803.3688011112043f  // ETA_A * log2(e)

#define PA_CONST 200000

// one 32B record per angular pair: g=(rx,ry,rz,d)  a=(fc, 1/d, spec_bits, pad)
struct __align__(32) PairRec { float4 g; float4 a; };
__device__ PairRec g_rec[PA_CONST];

// ================= kernel A: zero-fill || angular-pair precompute =================
__global__ __launch_bounds__(256)
void fusedA_kernel(const int* __restrict__ atom_index,
                   const int* __restrict__ pairs,   // [2, P]
                   const float* __restrict__ d_ij,  // [P]
                   const float* __restrict__ r_ij,  // [P,3]
                   float4* __restrict__ out4,
                   int P, int PA, int zblocks, int n4)
{
    if ((int)blockIdx.x < zblocks) {
        int stride = zblocks * 256;
        for (int i = blockIdx.x * 256 + threadIdx.x; i < n4; i += stride)
            out4[i] = make_float4(0.f, 0.f, 0.f, 0.f);
        return;
    }
    int p = (blockIdx.x - zblocks) * 256 + threadIdx.x;
    if (p >= PA) return;

    int i  = pairs[p];
    int j  = pairs[P + p];
    int si = atom_index[i];
    int sj = atom_index[j];
    float d = d_ij[p];

    PairRec r;
    r.g = make_float4(r_ij[3 * p + 0], r_ij[3 * p + 1], r_ij[3 * p + 2], d);
    float fc = (d < RCA) ? (0.5f * __cosf(PI_OVER_RCA * d) + 0.5f) : 0.0f;
    r.a = make_float4(fc, __fdividef(1.0f, d),
                      __int_as_float((si << 3) | sj), 0.0f);
    g_rec[p] = r;
}

// ================= kernel B: angular || radial, stripe-interleaved =================
__global__ __launch_bounds__(256)
void fusedB_kernel(const int* __restrict__ central,
                   const int* __restrict__ pidx,    // [2, T]
                   const int* __restrict__ sign12,  // [2, T]
                   const int* __restrict__ atom_index,
                   const int* __restrict__ pairs,   // [2, P]
                   const float* __restrict__ d_ij,
                   float* __restrict__ out,
                   int P, int T, int ablocks, int K)
{
    int b = blockIdx.x;
    int q = b / K;
    bool is_ang = ((b % K) == 0) && (q < ablocks);

    if (is_ang) {
        // ---------------- angular partition: 256 triples/block ----------------
        __shared__ float s_f1[256 * 4];   // pref * f1[zz]
        __shared__ float s_f2[256 * 8];   // f2[az]
        __shared__ int   s_base[256];

        int tid = threadIdx.x;
        int t0  = q * 256;
        int t   = t0 + tid;

        if (t < T) {
            int p0  = pidx[t];
            int p1  = pidx[T + t];
            int sg0 = sign12[t];
            int sg1 = sign12[T + t];
            int c   = central[t];

            PairRec r0 = g_rec[p0];
            PairRec r1 = g_rec[p1];

            float dot  = r0.g.x * r1.g.x + r0.g.y * r1.g.y + r0.g.z * r1.g.z;
            float ss   = (sg0 == sg1) ? 0.95f : -0.95f;
            float cosa = ss * dot * r0.a.y * r1.a.y;
            float sina = sqrtf(fmaxf(0.0f, 1.0f - cosa * cosa));
            float sd   = 0.5f * (r0.g.w + r1.g.w);
            float pref = 2.0f * r0.a.x * r1.a.x;

            // f1[zz] via cos(angle - shfz) = cosa*cos(shfz) + sina*sin(shfz)
            const float CZ[4] = { 0.92387953251f,  0.38268343236f,
                                 -0.38268343236f, -0.92387953251f };
            const float SZ[4] = { 0.38268343236f,  0.92387953251f,
                                  0.92387953251f,  0.38268343236f };
            #pragma unroll
            for (int zz = 0; zz < NZ; zz++) {
                float u = fmaxf(0.0f, fmaf(0.5f * CZ[zz], cosa,
                                      fmaf(0.5f * SZ[zz], sina, 0.5f)));
                s_f1[tid * 4 + zz] = pref * exp2f(ZETA * __log2f(u));
            }
            #pragma unroll
            for (int az = 0; az < NA; az++) {
                float dx = sd - (RAMIN + (float)az * DSTEP_A);
                s_f2[tid * 8 + az] = exp2f(-ETA_A_LOG2E * dx * dx);
            }

            int sp0 = __float_as_int(r0.a.z);
            int sp1 = __float_as_int(r1.a.z);
            int s0 = (sg0 > 0) ? (sp0 & 7) : (sp0 >> 3);
            int s1 = (sg1 > 0) ? (sp1 & 7) : (sp1 >> 3);
            int a  = min(s0, s1);
            int bb = max(s0, s1);
            int tri = a * S - ((a * (a - 1)) >> 1) + (bb - a);
            s_base[tid] = c * COLS + ANG_OFF + tri * SUB;
        }
        __syncthreads();

        int warp = tid >> 5;
        int lane = tid & 31;
        int az = lane >> 2;   // 0..7
        int zz = lane & 3;    // 0..3

        int begin = warp * 32;
        int nv = T - (t0 + begin);
        if (nv > 32) nv = 32;

        #pragma unroll 8
        for (int jj = 0; jj < nv; jj++) {
            int idx = begin + jj;
            float v = s_f1[idx * 4 + zz] * s_f2[idx * 8 + az];
            atomicAdd(out + s_base[idx] + lane, v);   // 128B coalesced RED
        }
    } else {
        // ---------------- radial partition: 16 pairs/block, 16 lanes/pair ------
        int nA_le = min(q + 1, ablocks);     // angular blocks with id <= b
        int rb = b - nA_le;
        int rtid = rb * 256 + threadIdx.x;
        int p = rtid >> 4;
        if (p >= P) return;
        int k = rtid & 15;

        int i = pairs[p];          // uniform within 16-lane group -> broadcast
        int j = pairs[P + p];
        int si = atom_index[i];
        int sj = atom_index[j];
        float d = __ldg(d_ij + p);

        float fc = (d < RC) ? (0.5f * __cosf(PI_OVER_RC * d) + 0.5f) : 0.0f;
        float dx = d - (RMIN + (float)k * DSTEP_R);
        float term = 0.25f * fc * __expf(-ETA_R * dx * dx);

        atomicAdd(out + i * COLS + sj * NRBF + k, term);  // 64B coalesced RED
        atomicAdd(out + j * COLS + si * NRBF + k, term);
    }
}

// ---------------- launch ----------------
extern "C" void kernel_launch(void* const* d_in, const int* in_sizes, int n_in,
                              void* d_out, int out_size)
{
    const int*   atom_index = (const int*)  d_in[0];
    const int*   pairs      = (const int*)  d_in[1];
    const float* d_ij       = (const float*)d_in[2];
    const float* r_ij       = (const float*)d_in[3];
    const int*   central    = (const int*)  d_in[4];
    const int*   pidx12     = (const int*)  d_in[5];
    const int*   sign12     = (const int*)  d_in[6];
    float* out = (float*)d_out;

    int P  = in_sizes[2];                 // pair count
    int T  = in_sizes[4];                 // triple count
    int PA = PA_CONST;
    if (PA > P) PA = P;

    // kernel A: zero-fill || angular prep
    int n4 = out_size / 4;
    int zblocks = 4736;
    int pblocks = (PA + 255) / 256;
    fusedA_kernel<<<zblocks + pblocks, 256>>>(atom_index, pairs, d_ij, r_ij,
                                              (float4*)d_out, P, PA, zblocks, n4);

    // kernel B: angular || radial, interleaved by stripes of K blocks
    int ablocks = (T + 255) / 256;
    int rblocks = (P * 16 + 255) / 256;   // 16 lanes per pair
    int total   = ablocks + rblocks;
    int K       = total / ablocks;
    if (K < 1) K = 1;
    fusedB_kernel<<<total, 256>>>(central, pidx12, sign12,
                                  atom_index, pairs, d_ij,
                                  out, P, T, ablocks, K);
}

// round 9
// speedup vs baseline: 1.4270x; 1.2305x over previous
#include <cuda_runtime.h>
#include <cstdint>

// ---------------- problem constants ----------------
#define NATOMS   50000
#define S        7
#define NRBF     16
#define NPAIRS   28        // S*(S+1)/2
#define SUB      32        // NA*NZ
#define COLS     1008      // S*NRBF + NPAIRS*SUB
#define ANG_OFF  112       // S*NRBF
#define RC       0.51f
#define RMIN     0.08f
#define RCA      0.35f
#define RAMIN    0.08f
#define NA       8
#define NZ       4
#define ETA_R    1970.0f
#define ZETA     14.1f
#define PI_F     3.14159265358979323846f
#define PI_OVER_RC   (PI_F / RC)
#define PI_OVER_RCA  (PI_F / RCA)
#define DSTEP_R  0.026875f       // (RC-RMIN)/NRBF
#define DSTEP_A  0.03375f        // (RCA-RAMIN)/NA
#define ETA_A_LOG2E 1803.3688011112043f  // ETA_A * log2(e)

#define PA_CONST 200000

// vector float atomic (sm_90+): one 16B reduction per lane
#define RED4(ptr, v)                                                          \
    asm volatile("red.global.add.v4.f32 [%0], {%1,%2,%3,%4};"                 \
                 :: "l"(ptr), "f"((v).x), "f"((v).y), "f"((v).z), "f"((v).w)  \
                 : "memory")

// one 32B record per angular pair: g=(rx,ry,rz,d)  a=(fc, 1/d, spec_bits, pad)
struct __align__(32) PairRec { float4 g; float4 a; };
__device__ PairRec g_rec[PA_CONST];

// ================= kernel A: zero-fill || angular-pair precompute =================
__global__ __launch_bounds__(256)
void fusedA_kernel(const int* __restrict__ atom_index,
                   const int* __restrict__ pairs,   // [2, P]
                   const float* __restrict__ d_ij,  // [P]
                   const float* __restrict__ r_ij,  // [P,3]
                   float4* __restrict__ out4,
                   int P, int PA, int zblocks, int n4)
{
    if ((int)blockIdx.x < zblocks) {
        int stride = zblocks * 256;
        for (int i = blockIdx.x * 256 + threadIdx.x; i < n4; i += stride)
            out4[i] = make_float4(0.f, 0.f, 0.f, 0.f);
        return;
    }
    int p = (blockIdx.x - zblocks) * 256 + threadIdx.x;
    if (p >= PA) return;

    int i  = pairs[p];
    int j  = pairs[P + p];
    int si = atom_index[i];
    int sj = atom_index[j];
    float d = d_ij[p];

    PairRec r;
    r.g = make_float4(r_ij[3 * p + 0], r_ij[3 * p + 1], r_ij[3 * p + 2], d);
    float fc = (d < RCA) ? (0.5f * __cosf(PI_OVER_RCA * d) + 0.5f) : 0.0f;
    r.a = make_float4(fc, __fdividef(1.0f, d),
                      __int_as_float((si << 3) | sj), 0.0f);
    g_rec[p] = r;
}

// ================= kernel B: angular || radial, Bresenham-interleaved =================
__global__ __launch_bounds__(256)
void fusedB_kernel(const int* __restrict__ central,
                   const int* __restrict__ pidx,    // [2, T]
                   const int* __restrict__ sign12,  // [2, T]
                   const int* __restrict__ atom_index,
                   const int* __restrict__ pairs,   // [2, P]
                   const float* __restrict__ d_ij,
                   float* __restrict__ out,
                   int P, int T, int ablocks, int total)
{
    int b = blockIdx.x;
    // Bresenham split: angular blocks spread evenly through the grid
    int a_lo = (int)((long long)b * ablocks / total);
    int a_hi = (int)(((long long)b + 1) * ablocks / total);
    bool is_ang = (a_hi > a_lo);

    if (is_ang) {
        // ---------------- angular partition: 256 triples/block ----------------
        __shared__ __align__(16) float s_f1[256 * 4];   // pref * f1[zz]
        __shared__ float s_f2[256 * 8];                 // f2[az]
        __shared__ int   s_base[256];

        int tid = threadIdx.x;
        int q   = a_lo;
        int t0  = q * 256;
        int t   = t0 + tid;

        if (t < T) {
            int p0  = pidx[t];
            int p1  = pidx[T + t];
            int sg0 = sign12[t];
            int sg1 = sign12[T + t];
            int c   = central[t];

            PairRec r0 = g_rec[p0];
            PairRec r1 = g_rec[p1];

            float dot  = r0.g.x * r1.g.x + r0.g.y * r1.g.y + r0.g.z * r1.g.z;
            float ss   = (sg0 == sg1) ? 0.95f : -0.95f;
            float cosa = ss * dot * r0.a.y * r1.a.y;
            float sina = sqrtf(fmaxf(0.0f, 1.0f - cosa * cosa));
            float sd   = 0.5f * (r0.g.w + r1.g.w);
            float pref = 2.0f * r0.a.x * r1.a.x;

            // f1[zz] via cos(angle - shfz) = cosa*cos(shfz) + sina*sin(shfz)
            const float CZ[4] = { 0.92387953251f,  0.38268343236f,
                                 -0.38268343236f, -0.92387953251f };
            const float SZ[4] = { 0.38268343236f,  0.92387953251f,
                                  0.92387953251f,  0.38268343236f };
            #pragma unroll
            for (int zz = 0; zz < NZ; zz++) {
                float u = fmaxf(0.0f, fmaf(0.5f * CZ[zz], cosa,
                                      fmaf(0.5f * SZ[zz], sina, 0.5f)));
                s_f1[tid * 4 + zz] = pref * exp2f(ZETA * __log2f(u));
            }
            #pragma unroll
            for (int az = 0; az < NA; az++) {
                float dx = sd - (RAMIN + (float)az * DSTEP_A);
                s_f2[tid * 8 + az] = exp2f(-ETA_A_LOG2E * dx * dx);
            }

            int sp0 = __float_as_int(r0.a.z);
            int sp1 = __float_as_int(r1.a.z);
            int s0 = (sg0 > 0) ? (sp0 & 7) : (sp0 >> 3);
            int s1 = (sg1 > 0) ? (sp1 & 7) : (sp1 >> 3);
            int a  = min(s0, s1);
            int bb = max(s0, s1);
            int tri = a * S - ((a * (a - 1)) >> 1) + (bb - a);
            s_base[tid] = c * COLS + ANG_OFF + tri * SUB;
        }
        __syncwarp();   // phase-2 reads only this warp's slice

        // warp phase: 4 triples per warp-instruction, 16B red.v4 per lane
        int lane = tid & 31;
        int warp = tid >> 5;
        int sub  = lane >> 3;     // triple slot 0..3
        int az   = lane & 7;      // shfa index 0..7
        int begin = warp * 32;
        int limit = T - t0;       // triples valid in this block (<=256)
        if (limit > 256) limit = 256;

        #pragma unroll
        for (int jj = 0; jj < 8; jj++) {
            int idx = begin + jj * 4 + sub;
            if (idx < limit) {
                int base = s_base[idx];
                float f2v  = s_f2[idx * 8 + az];
                float4 f1v = *(const float4*)&s_f1[idx * 4];
                float4 v = make_float4(f2v * f1v.x, f2v * f1v.y,
                                       f2v * f1v.z, f2v * f1v.w);
                RED4(out + base + az * 4, v);   // 8 lanes -> 128B contiguous
            }
        }
    } else {
        // ---------------- radial partition: 4 lanes/pair, red.v4 ----------------
        int rid  = b - a_hi;                 // contiguous radial block id
        int rtid = rid * 256 + threadIdx.x;
        int p = rtid >> 2;
        if (p >= P) return;
        int m = rtid & 3;                    // bin group 0..3 (4 bins each)

        int i = pairs[p];                    // broadcast within 4-lane group
        int j = pairs[P + p];
        int si = atom_index[i];
        int sj = atom_index[j];
        float d = __ldg(d_ij + p);

        // 0.25 * (0.5*cos + 0.5) = 0.125*cos + 0.125   (R8 bug: had 0.25/0.25)
        float fc = (d < RC) ? (0.125f * __cosf(PI_OVER_RC * d) + 0.125f) : 0.0f;
        int k0 = m * 4;
        float4 v;
        {
            float dx0 = d - (RMIN + (float)(k0 + 0) * DSTEP_R);
            float dx1 = d - (RMIN + (float)(k0 + 1) * DSTEP_R);
            float dx2 = d - (RMIN + (float)(k0 + 2) * DSTEP_R);
            float dx3 = d - (RMIN + (float)(k0 + 3) * DSTEP_R);
            v.x = fc * __expf(-ETA_R * dx0 * dx0);
            v.y = fc * __expf(-ETA_R * dx1 * dx1);
            v.z = fc * __expf(-ETA_R * dx2 * dx2);
            v.w = fc * __expf(-ETA_R * dx3 * dx3);
        }
        RED4(out + i * COLS + sj * NRBF + k0, v);   // 4 lanes -> 64B contiguous
        RED4(out + j * COLS + si * NRBF + k0, v);
    }
}

// ---------------- launch ----------------
extern "C" void kernel_launch(void* const* d_in, const int* in_sizes, int n_in,
                              void* d_out, int out_size)
{
    const int*   atom_index = (const int*)  d_in[0];
    const int*   pairs      = (const int*)  d_in[1];
    const float* d_ij       = (const float*)d_in[2];
    const float* r_ij       = (const float*)d_in[3];
    const int*   central    = (const int*)  d_in[4];
    const int*   pidx12     = (const int*)  d_in[5];
    const int*   sign12     = (const int*)  d_in[6];
    float* out = (float*)d_out;

    int P  = in_sizes[2];                 // pair count
    int T  = in_sizes[4];                 // triple count
    int PA = PA_CONST;
    if (PA > P) PA = P;

    // kernel A: zero-fill || angular prep
    int n4 = out_size / 4;
    int zblocks = 4736;
    int pblocks = (PA + 255) / 256;
    fusedA_kernel<<<zblocks + pblocks, 256>>>(atom_index, pairs, d_ij, r_ij,
                                              (float4*)d_out, P, PA, zblocks, n4);

    // kernel B: angular || radial, Bresenham-interleaved
    int ablocks = (T + 255) / 256;
    int rblocks = (P * 4 + 255) / 256;    // 4 lanes per pair
    int total   = ablocks + rblocks;
    fusedB_kernel<<<total, 256>>>(central, pidx12, sign12,
                                  atom_index, pairs, d_ij,
                                  out, P, T, ablocks, total);
}